// round 8
// baseline (speedup 1.0000x reference)
#include <cuda_runtime.h>
#include <math.h>

#define NN 50000          // nodes
#define NF 128            // feature width (layer-1 in, layer-2 out)
#define NH 256            // hidden width
#define EMAX 800000
#define PMAX 100000
#define SCAN_B 1024
#define NBLK ((NN + SCAN_B - 1) / SCAN_B)   // 49

// ---- scratch (device globals; no allocation allowed) ----
__device__ int   g_row [EMAX];
__device__ int   g_col [EMAX];
__device__ int   g_eidx[EMAX];              // CSR: src node per (dst-sorted) slot
__device__ int   g_cnt [NN];                // in-degree (no self loop)
__device__ int   g_cur [NN];                // fill cursors
__device__ int   g_rowptr[NN + 1];
__device__ int   g_bsum[NBLK];
__device__ int   g_ma  [PMAX];
__device__ int   g_mb  [PMAX];
__device__ float g_dinv[NN];
__device__ float g_Y1  [(size_t)NN * NF];   // S @ X
__device__ float g_H1  [(size_t)NN * NH];   // relu(Y1 @ W1 + b1)
__device__ float g_Z   [(size_t)NN * NF];   // H1 @ W2
__device__ float g_H2  [(size_t)NN * NF];   // S @ Z + b2

// ---------------------------------------------------- helpers
// Per-thread dtype sniff: int64 node ids are all in [0, NN); int32 data
// viewed as int64 fuses random pairs into huge values (hi word nonzero
// w.p. 1 - 2e-5 per sample; 8 samples => certain). Head loads broadcast
// from L1, ~free.
__device__ __forceinline__ int sniff_is64(const void* p_) {
    const long long* p = (const long long*)p_;
    int ok = 1;
#pragma unroll
    for (int i = 0; i < 8; i++) {
        long long v = p[i];
        if (v < 0 || v >= NN) ok = 0;
    }
    return ok;
}

__global__ void k_zero_cnt() {
    int i = blockIdx.x * blockDim.x + threadIdx.x;
    if (i < NN) { g_cnt[i] = 0; g_cur[i] = 0; }
}

// one kernel: convert edges (+count in-degree) AND convert mask pairs
__global__ void k_convert(const void* __restrict__ ei, int E,
                          const void* __restrict__ mask, int P, int EB) {
    int b = blockIdx.x;
    if (b < EB) {
        int e = b * blockDim.x + threadIdx.x;
        if (e >= E) return;
        int r, c;
        if (sniff_is64(ei)) {
            const long long* p = (const long long*)ei;
            r = (int)p[e];
            c = (int)p[(size_t)E + e];
        } else {
            const int* p = (const int*)ei;
            r = p[e];
            c = p[E + e];
        }
        g_row[e] = r;
        g_col[e] = c;
        atomicAdd(&g_cnt[c], 1);
    } else {
        int i = (b - EB) * blockDim.x + threadIdx.x;
        if (i >= P) return;
        int a, c;
        if (sniff_is64(mask)) {
            const long long* p = (const long long*)mask;
            a = (int)p[(size_t)i * 2 + 0];
            c = (int)p[(size_t)i * 2 + 1];
        } else {
            const int* p = (const int*)mask;
            a = p[i * 2 + 0];
            c = p[i * 2 + 1];
        }
        g_ma[i] = a;
        g_mb[i] = c;
    }
}

// ------------------------------------------------- exclusive scan (2-phase)
__global__ __launch_bounds__(SCAN_B)
void k_scan_block() {
    __shared__ int sh[SCAN_B];
    int t = threadIdx.x;
    int idx = blockIdx.x * SCAN_B + t;
    int v = (idx < NN) ? g_cnt[idx] : 0;
    sh[t] = v;
    __syncthreads();
    for (int off = 1; off < SCAN_B; off <<= 1) {
        int add = (t >= off) ? sh[t - off] : 0;
        __syncthreads();
        sh[t] += add;
        __syncthreads();
    }
    if (idx < NN) g_rowptr[idx] = sh[t] - v;      // exclusive within block
    if (t == SCAN_B - 1) g_bsum[blockIdx.x] = sh[t];
}

// single block: block-sum prefix + rowptr fixup + dinv, all in one launch
__global__ __launch_bounds__(SCAN_B)
void k_scan_finish(int E) {
    __shared__ int pre[NBLK];
    int t = threadIdx.x;
    if (t == 0) {
        int acc = 0;
#pragma unroll
        for (int b = 0; b < NBLK; b++) {
            pre[b] = acc;
            acc += g_bsum[b];
        }
    }
    __syncthreads();
    for (int idx = t; idx < NN; idx += SCAN_B) {
        g_rowptr[idx] += pre[idx >> 10];
        g_dinv[idx] = rsqrtf((float)g_cnt[idx] + 1.0f);   // + self loop
    }
    if (t == 0) g_rowptr[NN] = E;
}

// ------------------------------------------------------------- CSR fill
__global__ void k_fill(int E) {
    int e = blockIdx.x * blockDim.x + threadIdx.x;
    if (e >= E) return;
    int c = g_col[e];
    int pos = g_rowptr[c] + atomicAdd(&g_cur[c], 1);
    g_eidx[pos] = g_row[e];
}

// ----------------------------------------------------------------- gather
// warp per node: dst[n] = dinv[n]^2*src[n] + sum_e dinv[r]*dinv[n]*src[r] (+bias)
__global__ __launch_bounds__(256)
void k_gather(const float* __restrict__ src, float* __restrict__ dst,
              const float* __restrict__ bias) {
    int node = (blockIdx.x * blockDim.x + threadIdx.x) >> 5;
    if (node >= NN) return;
    int lane = threadIdx.x & 31;
    float dc = g_dinv[node];

    float4 v = ((const float4*)(src + (size_t)node * NF))[lane];
    float ws = dc * dc;
    float4 acc;
    acc.x = ws * v.x; acc.y = ws * v.y; acc.z = ws * v.z; acc.w = ws * v.w;

    int beg = g_rowptr[node];
    int end = g_rowptr[node + 1];
#pragma unroll 4
    for (int j = beg; j < end; j++) {
        int r = __ldg(&g_eidx[j]);
        float w = __ldg(&g_dinv[r]) * dc;
        float4 u = ((const float4*)(src + (size_t)r * NF))[lane];
        acc.x += w * u.x; acc.y += w * u.y;
        acc.z += w * u.z; acc.w += w * u.w;
    }
    if (bias) {
        float4 b = ((const float4*)bias)[lane];
        acc.x += b.x; acc.y += b.y; acc.z += b.z; acc.w += b.w;
    }
    ((float4*)(dst + (size_t)node * NF))[lane] = acc;
}

// ------------------------------------------------------------------ SGEMM
// C[M,N] = A[M,K] @ B[K,N]  (+bias per col)  (optional relu)
// 128x128 tile, BK=16, double-buffered smem, 1 barrier/iter, 8x8 micro-tile
__global__ __launch_bounds__(256, 2)
void k_sgemm(const float* __restrict__ A, const float* __restrict__ B,
             const float* __restrict__ bias, float* __restrict__ C,
             int M, int N, int K, int relu) {
    const int BM = 128, BN = 128, BK = 16;
    __shared__ float As[2][BK * BM];   // transposed: As[k][m]
    __shared__ float Bs[2][BK * BN];   // Bs[k][n]

    int tid = threadIdx.x;
    int tx = tid & 15;
    int ty = tid >> 4;
    int rowBlock = blockIdx.x * BM;
    int colBlock = blockIdx.y * BN;

    // per-thread staging slots (2 float4 for A, 2 for B)
    int fi0 = tid, fi1 = tid + 256;
    int ar0 = fi0 >> 2,  ak0 = (fi0 & 3) << 2;
    int ar1 = fi1 >> 2,  ak1 = (fi1 & 3) << 2;
    int bk0 = fi0 >> 5,  bn0 = (fi0 & 31) << 2;
    int bk1 = fi1 >> 5,  bn1 = (fi1 & 31) << 2;

    float4 ra0, ra1, rb0, rb1;

    auto load_g = [&](int k0) {
        ra0 = make_float4(0.f, 0.f, 0.f, 0.f);
        ra1 = make_float4(0.f, 0.f, 0.f, 0.f);
        int g0 = rowBlock + ar0, g1 = rowBlock + ar1;
        if (g0 < M) ra0 = *(const float4*)(A + (size_t)g0 * K + k0 + ak0);
        if (g1 < M) ra1 = *(const float4*)(A + (size_t)g1 * K + k0 + ak1);
        rb0 = *(const float4*)(B + (size_t)(k0 + bk0) * N + colBlock + bn0);
        rb1 = *(const float4*)(B + (size_t)(k0 + bk1) * N + colBlock + bn1);
    };
    auto store_s = [&](int buf) {
        As[buf][(ak0 + 0) * BM + ar0] = ra0.x;
        As[buf][(ak0 + 1) * BM + ar0] = ra0.y;
        As[buf][(ak0 + 2) * BM + ar0] = ra0.z;
        As[buf][(ak0 + 3) * BM + ar0] = ra0.w;
        As[buf][(ak1 + 0) * BM + ar1] = ra1.x;
        As[buf][(ak1 + 1) * BM + ar1] = ra1.y;
        As[buf][(ak1 + 2) * BM + ar1] = ra1.z;
        As[buf][(ak1 + 3) * BM + ar1] = ra1.w;
        *(float4*)&Bs[buf][bk0 * BN + bn0] = rb0;
        *(float4*)&Bs[buf][bk1 * BN + bn1] = rb1;
    };

    float acc[8][8];
#pragma unroll
    for (int i = 0; i < 8; i++)
#pragma unroll
        for (int j = 0; j < 8; j++) acc[i][j] = 0.0f;

    load_g(0);
    store_s(0);
    __syncthreads();

    int buf = 0;
    for (int k0 = 0; k0 < K; k0 += BK) {
        bool more = (k0 + BK) < K;
        if (more) load_g(k0 + BK);      // in flight during compute below

#pragma unroll
        for (int kk = 0; kk < BK; kk++) {
            float a0[4], a1[4], b0[4], b1[4];
            *(float4*)a0 = *(const float4*)&As[buf][kk * BM + ty * 4];
            *(float4*)a1 = *(const float4*)&As[buf][kk * BM + 64 + ty * 4];
            *(float4*)b0 = *(const float4*)&Bs[buf][kk * BN + tx * 4];
            *(float4*)b1 = *(const float4*)&Bs[buf][kk * BN + 64 + tx * 4];
#pragma unroll
            for (int i = 0; i < 4; i++) {
#pragma unroll
                for (int j = 0; j < 4; j++) {
                    acc[i][j]         += a0[i] * b0[j];
                    acc[i][j + 4]     += a0[i] * b1[j];
                    acc[i + 4][j]     += a1[i] * b0[j];
                    acc[i + 4][j + 4] += a1[i] * b1[j];
                }
            }
        }
        if (more) {
            store_s(buf ^ 1);           // disjoint buffer: no hazard w/ compute
            __syncthreads();
            buf ^= 1;
        }
    }

#pragma unroll
    for (int ih = 0; ih < 2; ih++) {
#pragma unroll
        for (int i = 0; i < 4; i++) {
            int row = rowBlock + ih * 64 + ty * 4 + i;
            if (row >= M) continue;
#pragma unroll
            for (int jh = 0; jh < 2; jh++) {
                int col = colBlock + jh * 64 + tx * 4;
                float* a = &acc[ih * 4 + i][jh * 4];
                float4 o = make_float4(a[0], a[1], a[2], a[3]);
                if (bias) {
                    float4 b = *(const float4*)(bias + col);
                    o.x += b.x; o.y += b.y; o.z += b.z; o.w += b.w;
                }
                if (relu) {
                    o.x = fmaxf(o.x, 0.f); o.y = fmaxf(o.y, 0.f);
                    o.z = fmaxf(o.z, 0.f); o.w = fmaxf(o.w, 0.f);
                }
                *(float4*)(C + (size_t)row * N + col) = o;
            }
        }
    }
}

// --------------------------------------------------------------- pair dot
__global__ void k_pairs(const float* __restrict__ Wl,
                        const float* __restrict__ bl,
                        float* __restrict__ out, int P) {
    int warp = (blockIdx.x * blockDim.x + threadIdx.x) >> 5;
    if (warp >= P) return;
    int lane = threadIdx.x & 31;
    int a = g_ma[warp];
    int b = g_mb[warp];
    float4 va = ((const float4*)(g_H2 + (size_t)a * NF))[lane];
    float4 wa = ((const float4*)Wl)[lane];
    float4 vb = ((const float4*)(g_H2 + (size_t)b * NF))[lane];
    float4 wb = ((const float4*)(Wl + NF))[lane];
    float acc = va.x * wa.x + va.y * wa.y + va.z * wa.z + va.w * wa.w
              + vb.x * wb.x + vb.y * wb.y + vb.z * wb.z + vb.w * wb.w;
#pragma unroll
    for (int o = 16; o > 0; o >>= 1) acc += __shfl_xor_sync(0xffffffffu, acc, o);
    if (lane == 0) out[warp] = 1.0f / (1.0f + expf(-(acc + bl[0])));
}

// ------------------------------------------------------------------ launch
extern "C" void kernel_launch(void* const* d_in, const int* in_sizes, int n_in,
                              void* d_out, int out_size) {
    const void*  ei   = d_in[0];                 // [2, E] int32 or int64
    const float* X    = (const float*)d_in[1];   // [NN, 128]
    const void*  mask = d_in[2];                 // [P, 2] int32 or int64
    const float* W1   = (const float*)d_in[3];   // [128, 256]
    const float* b1   = (const float*)d_in[4];   // [256]
    const float* W2   = (const float*)d_in[5];   // [256, 128]
    const float* b2   = (const float*)d_in[6];   // [128]
    const float* Wl   = (const float*)d_in[7];   // [256, 1]
    const float* bl   = (const float*)d_in[8];   // [1]
    float* out = (float*)d_out;

    int E = in_sizes[0] / 2;
    int P = out_size;

    float *Y1, *H1, *Z, *H2;
    cudaGetSymbolAddress((void**)&Y1, g_Y1);
    cudaGetSymbolAddress((void**)&H1, g_H1);
    cudaGetSymbolAddress((void**)&Z,  g_Z);
    cudaGetSymbolAddress((void**)&H2, g_H2);

    const int T = 256;
    int EB = (E + T - 1) / T;
    int PB = (P + T - 1) / T;

    // prologue: 5 launches
    k_zero_cnt   <<<(NN + T - 1) / T, T>>>();
    k_convert    <<<EB + PB, T>>>(ei, E, mask, P, EB);
    k_scan_block <<<NBLK, SCAN_B>>>();
    k_scan_finish<<<1, SCAN_B>>>(E);
    k_fill       <<<EB, T>>>(E);

    // layer 1: Y1 = S @ X ; H1 = relu(Y1 @ W1 + b1)
    k_gather<<<(NN * 32 + T - 1) / T, T>>>(X, Y1, nullptr);
    k_sgemm<<<dim3((NN + 127) / 128, NH / 128), 256>>>(Y1, W1, b1, H1,
                                                       NN, NH, NF, 1);

    // layer 2: Z = H1 @ W2 ; H2 = S @ Z + b2
    k_sgemm<<<dim3((NN + 127) / 128, NF / 128), 256>>>(H1, W2, nullptr, Z,
                                                       NN, NF, NH, 0);
    k_gather<<<(NN * 32 + T - 1) / T, T>>>(Z, H2, b2);

    // link prediction
    k_pairs<<<(int)(((size_t)P * 32 + T - 1) / T), T>>>(Wl, bl, out, P);
}

// round 10
// speedup vs baseline: 1.0753x; 1.0753x over previous
#include <cuda_runtime.h>
#include <math.h>

#define NN 50000          // nodes
#define NF 128            // feature width (layer-1 in, layer-2 out)
#define NH 256            // hidden width
#define EMAX 800000
#define PMAX 100000
#define SCAN_B 1024
#define NBLK ((NN + SCAN_B - 1) / SCAN_B)   // 49

// ---- scratch (device globals; no allocation allowed) ----
__device__ int   g_row [EMAX];
__device__ int   g_col [EMAX];
__device__ int   g_eidx[EMAX];              // CSR: src node per (dst-sorted) slot
__device__ int   g_cnt [NN];                // in-degree (no self loop)
__device__ int   g_cur [NN];                // fill cursors
__device__ int   g_rowptr[NN + 1];
__device__ int   g_bsum[NBLK];
__device__ int   g_ma  [PMAX];
__device__ int   g_mb  [PMAX];
__device__ float g_dinv[NN];
__device__ float g_Y1  [(size_t)NN * NF];   // S @ X
__device__ float g_H1  [(size_t)NN * NH];   // relu(Y1 @ W1 + b1)
__device__ float g_Z   [(size_t)NN * NF];   // H1 @ W2
__device__ float g_H2  [(size_t)NN * NF];   // S @ Z + b2

// ---------------------------------------------------- helpers
// Per-thread dtype sniff: int64 node ids are all in [0, NN); int32 data
// viewed as int64 fuses random pairs into huge values. 8 samples => certain.
__device__ __forceinline__ int sniff_is64(const void* p_) {
    const long long* p = (const long long*)p_;
    int ok = 1;
#pragma unroll
    for (int i = 0; i < 8; i++) {
        long long v = p[i];
        if (v < 0 || v >= NN) ok = 0;
    }
    return ok;
}

__global__ void k_zero_cnt() {
    int i = blockIdx.x * blockDim.x + threadIdx.x;
    if (i < NN) { g_cnt[i] = 0; g_cur[i] = 0; }
}

// one kernel: convert edges (+count in-degree) AND convert mask pairs
__global__ void k_convert(const void* __restrict__ ei, int E,
                          const void* __restrict__ mask, int P, int EB) {
    int b = blockIdx.x;
    if (b < EB) {
        int e = b * blockDim.x + threadIdx.x;
        if (e >= E) return;
        int r, c;
        if (sniff_is64(ei)) {
            const long long* p = (const long long*)ei;
            r = (int)p[e];
            c = (int)p[(size_t)E + e];
        } else {
            const int* p = (const int*)ei;
            r = p[e];
            c = p[E + e];
        }
        g_row[e] = r;
        g_col[e] = c;
        atomicAdd(&g_cnt[c], 1);
    } else {
        int i = (b - EB) * blockDim.x + threadIdx.x;
        if (i >= P) return;
        int a, c;
        if (sniff_is64(mask)) {
            const long long* p = (const long long*)mask;
            a = (int)p[(size_t)i * 2 + 0];
            c = (int)p[(size_t)i * 2 + 1];
        } else {
            const int* p = (const int*)mask;
            a = p[i * 2 + 0];
            c = p[i * 2 + 1];
        }
        g_ma[i] = a;
        g_mb[i] = c;
    }
}

// ------------------------------------------------- exclusive scan (3-phase)
__global__ __launch_bounds__(SCAN_B)
void k_scan_block() {
    __shared__ int sh[SCAN_B];
    int t = threadIdx.x;
    int idx = blockIdx.x * SCAN_B + t;
    int v = (idx < NN) ? g_cnt[idx] : 0;
    sh[t] = v;
    __syncthreads();
    for (int off = 1; off < SCAN_B; off <<= 1) {
        int add = (t >= off) ? sh[t - off] : 0;
        __syncthreads();
        sh[t] += add;
        __syncthreads();
    }
    if (idx < NN) g_rowptr[idx] = sh[t] - v;      // exclusive within block
    if (t == SCAN_B - 1) g_bsum[blockIdx.x] = sh[t];
}

// tiny: exclusive-prefix the 49 block sums (two warps, shfl scan)
__global__ void k_scan_sums() {
    int t = threadIdx.x;                    // 64 threads, NBLK=49 active
    int v = (t < NBLK) ? g_bsum[t] : 0;
    int lane = t & 31, w = t >> 5;
    int x = v;
#pragma unroll
    for (int off = 1; off < 32; off <<= 1) {
        int y = __shfl_up_sync(0xffffffffu, x, off);
        if (lane >= off) x += y;
    }
    __shared__ int wsum[2];
    if (lane == 31) wsum[w] = x;
    __syncthreads();
    int base = (w == 1) ? wsum[0] : 0;
    if (t < NBLK) g_bsum[t] = base + x - v;  // exclusive
}

// grid-wide: rowptr fixup + dinv (parallel across all SMs)
__global__ void k_finish(int E) {
    int idx = blockIdx.x * blockDim.x + threadIdx.x;
    if (idx < NN) {
        g_rowptr[idx] += g_bsum[idx >> 10];
        g_dinv[idx] = rsqrtf((float)g_cnt[idx] + 1.0f);   // + self loop
    }
    if (idx == 0) g_rowptr[NN] = E;
}

// ------------------------------------------------------------- CSR fill
__global__ void k_fill(int E) {
    int e = blockIdx.x * blockDim.x + threadIdx.x;
    if (e >= E) return;
    int c = g_col[e];
    int pos = g_rowptr[c] + atomicAdd(&g_cur[c], 1);
    g_eidx[pos] = g_row[e];
}

// ----------------------------------------------------------------- gather
// warp per node: dst[n] = dinv[n]^2*src[n] + sum_e dinv[r]*dinv[n]*src[r] (+bias)
__global__ __launch_bounds__(256)
void k_gather(const float* __restrict__ src, float* __restrict__ dst,
              const float* __restrict__ bias) {
    int node = (blockIdx.x * blockDim.x + threadIdx.x) >> 5;
    if (node >= NN) return;
    int lane = threadIdx.x & 31;
    float dc = g_dinv[node];

    float4 v = ((const float4*)(src + (size_t)node * NF))[lane];
    float ws = dc * dc;
    float4 acc;
    acc.x = ws * v.x; acc.y = ws * v.y; acc.z = ws * v.z; acc.w = ws * v.w;

    int beg = g_rowptr[node];
    int end = g_rowptr[node + 1];
#pragma unroll 4
    for (int j = beg; j < end; j++) {
        int r = __ldg(&g_eidx[j]);
        float w = __ldg(&g_dinv[r]) * dc;
        float4 u = ((const float4*)(src + (size_t)r * NF))[lane];
        acc.x += w * u.x; acc.y += w * u.y;
        acc.z += w * u.z; acc.w += w * u.w;
    }
    if (bias) {
        float4 b = ((const float4*)bias)[lane];
        acc.x += b.x; acc.y += b.y; acc.z += b.z; acc.w += b.w;
    }
    ((float4*)(dst + (size_t)node * NF))[lane] = acc;
}

// ------------------------------------------------------------------ SGEMM
// C[M,N] = A[M,K] @ B[K,N]  (+bias per col)  (optional relu)
// 128x128 tile, BK=16, double-buffered smem, 1 barrier/iter, 8x8 micro-tile
__global__ __launch_bounds__(256, 2)
void k_sgemm(const float* __restrict__ A, const float* __restrict__ B,
             const float* __restrict__ bias, float* __restrict__ C,
             int M, int N, int K, int relu) {
    const int BM = 128, BN = 128, BK = 16;
    __shared__ float As[2][BK * BM];   // transposed: As[k][m]
    __shared__ float Bs[2][BK * BN];   // Bs[k][n]

    int tid = threadIdx.x;
    int tx = tid & 15;
    int ty = tid >> 4;
    int rowBlock = blockIdx.x * BM;
    int colBlock = blockIdx.y * BN;

    int fi0 = tid, fi1 = tid + 256;
    int ar0 = fi0 >> 2,  ak0 = (fi0 & 3) << 2;
    int ar1 = fi1 >> 2,  ak1 = (fi1 & 3) << 2;
    int bk0 = fi0 >> 5,  bn0 = (fi0 & 31) << 2;
    int bk1 = fi1 >> 5,  bn1 = (fi1 & 31) << 2;

    float4 ra0, ra1, rb0, rb1;

    auto load_g = [&](int k0) {
        ra0 = make_float4(0.f, 0.f, 0.f, 0.f);
        ra1 = make_float4(0.f, 0.f, 0.f, 0.f);
        int g0 = rowBlock + ar0, g1 = rowBlock + ar1;
        if (g0 < M) ra0 = *(const float4*)(A + (size_t)g0 * K + k0 + ak0);
        if (g1 < M) ra1 = *(const float4*)(A + (size_t)g1 * K + k0 + ak1);
        rb0 = *(const float4*)(B + (size_t)(k0 + bk0) * N + colBlock + bn0);
        rb1 = *(const float4*)(B + (size_t)(k0 + bk1) * N + colBlock + bn1);
    };
    auto store_s = [&](int buf) {
        As[buf][(ak0 + 0) * BM + ar0] = ra0.x;
        As[buf][(ak0 + 1) * BM + ar0] = ra0.y;
        As[buf][(ak0 + 2) * BM + ar0] = ra0.z;
        As[buf][(ak0 + 3) * BM + ar0] = ra0.w;
        As[buf][(ak1 + 0) * BM + ar1] = ra1.x;
        As[buf][(ak1 + 1) * BM + ar1] = ra1.y;
        As[buf][(ak1 + 2) * BM + ar1] = ra1.z;
        As[buf][(ak1 + 3) * BM + ar1] = ra1.w;
        *(float4*)&Bs[buf][bk0 * BN + bn0] = rb0;
        *(float4*)&Bs[buf][bk1 * BN + bn1] = rb1;
    };

    float acc[8][8];
#pragma unroll
    for (int i = 0; i < 8; i++)
#pragma unroll
        for (int j = 0; j < 8; j++) acc[i][j] = 0.0f;

    load_g(0);
    store_s(0);
    __syncthreads();

    int buf = 0;
    for (int k0 = 0; k0 < K; k0 += BK) {
        bool more = (k0 + BK) < K;
        if (more) load_g(k0 + BK);

#pragma unroll
        for (int kk = 0; kk < BK; kk++) {
            float a0[4], a1[4], b0[4], b1[4];
            *(float4*)a0 = *(const float4*)&As[buf][kk * BM + ty * 4];
            *(float4*)a1 = *(const float4*)&As[buf][kk * BM + 64 + ty * 4];
            *(float4*)b0 = *(const float4*)&Bs[buf][kk * BN + tx * 4];
            *(float4*)b1 = *(const float4*)&Bs[buf][kk * BN + 64 + tx * 4];
#pragma unroll
            for (int i = 0; i < 4; i++) {
#pragma unroll
                for (int j = 0; j < 4; j++) {
                    acc[i][j]         += a0[i] * b0[j];
                    acc[i][j + 4]     += a0[i] * b1[j];
                    acc[i + 4][j]     += a1[i] * b0[j];
                    acc[i + 4][j + 4] += a1[i] * b1[j];
                }
            }
        }
        if (more) {
            store_s(buf ^ 1);
            __syncthreads();
            buf ^= 1;
        }
    }

#pragma unroll
    for (int ih = 0; ih < 2; ih++) {
#pragma unroll
        for (int i = 0; i < 4; i++) {
            int row = rowBlock + ih * 64 + ty * 4 + i;
            if (row >= M) continue;
#pragma unroll
            for (int jh = 0; jh < 2; jh++) {
                int col = colBlock + jh * 64 + tx * 4;
                float* a = &acc[ih * 4 + i][jh * 4];
                float4 o = make_float4(a[0], a[1], a[2], a[3]);
                if (bias) {
                    float4 b = *(const float4*)(bias + col);
                    o.x += b.x; o.y += b.y; o.z += b.z; o.w += b.w;
                }
                if (relu) {
                    o.x = fmaxf(o.x, 0.f); o.y = fmaxf(o.y, 0.f);
                    o.z = fmaxf(o.z, 0.f); o.w = fmaxf(o.w, 0.f);
                }
                *(float4*)(C + (size_t)row * N + col) = o;
            }
        }
    }
}

// --------------------------------------------------------------- pair dot
__global__ void k_pairs(const float* __restrict__ Wl,
                        const float* __restrict__ bl,
                        float* __restrict__ out, int P) {
    int warp = (blockIdx.x * blockDim.x + threadIdx.x) >> 5;
    if (warp >= P) return;
    int lane = threadIdx.x & 31;
    int a = g_ma[warp];
    int b = g_mb[warp];
    float4 va = ((const float4*)(g_H2 + (size_t)a * NF))[lane];
    float4 wa = ((const float4*)Wl)[lane];
    float4 vb = ((const float4*)(g_H2 + (size_t)b * NF))[lane];
    float4 wb = ((const float4*)(Wl + NF))[lane];
    float acc = va.x * wa.x + va.y * wa.y + va.z * wa.z + va.w * wa.w
              + vb.x * wb.x + vb.y * wb.y + vb.z * wb.z + vb.w * wb.w;
#pragma unroll
    for (int o = 16; o > 0; o >>= 1) acc += __shfl_xor_sync(0xffffffffu, acc, o);
    if (lane == 0) out[warp] = 1.0f / (1.0f + expf(-(acc + bl[0])));
}

// ------------------------------------------------------------------ launch
extern "C" void kernel_launch(void* const* d_in, const int* in_sizes, int n_in,
                              void* d_out, int out_size) {
    const void*  ei   = d_in[0];                 // [2, E] int32 or int64
    const float* X    = (const float*)d_in[1];   // [NN, 128]
    const void*  mask = d_in[2];                 // [P, 2] int32 or int64
    const float* W1   = (const float*)d_in[3];   // [128, 256]
    const float* b1   = (const float*)d_in[4];   // [256]
    const float* W2   = (const float*)d_in[5];   // [256, 128]
    const float* b2   = (const float*)d_in[6];   // [128]
    const float* Wl   = (const float*)d_in[7];   // [256, 1]
    const float* bl   = (const float*)d_in[8];   // [1]
    float* out = (float*)d_out;

    int E = in_sizes[0] / 2;
    int P = out_size;

    float *Y1, *H1, *Z, *H2;
    cudaGetSymbolAddress((void**)&Y1, g_Y1);
    cudaGetSymbolAddress((void**)&H1, g_H1);
    cudaGetSymbolAddress((void**)&Z,  g_Z);
    cudaGetSymbolAddress((void**)&H2, g_H2);

    const int T = 256;
    int EB = (E + T - 1) / T;
    int PB = (P + T - 1) / T;

    // prologue: 6 launches (all parallel-wide except the 49-elem scan_sums)
    k_zero_cnt  <<<(NN + T - 1) / T, T>>>();
    k_convert   <<<EB + PB, T>>>(ei, E, mask, P, EB);
    k_scan_block<<<NBLK, SCAN_B>>>();
    k_scan_sums <<<1, 64>>>();
    k_finish    <<<(NN + T - 1) / T, T>>>(E);
    k_fill      <<<EB, T>>>(E);

    // layer 1: Y1 = S @ X ; H1 = relu(Y1 @ W1 + b1)
    k_gather<<<(NN * 32 + T - 1) / T, T>>>(X, Y1, nullptr);
    k_sgemm<<<dim3((NN + 127) / 128, NH / 128), 256>>>(Y1, W1, b1, H1,
                                                       NN, NH, NF, 1);

    // layer 2: Z = H1 @ W2 ; H2 = S @ Z + b2
    k_sgemm<<<dim3((NN + 127) / 128, NF / 128), 256>>>(H1, W2, nullptr, Z,
                                                       NN, NF, NH, 0);
    k_gather<<<(NN * 32 + T - 1) / T, T>>>(Z, H2, b2);

    // link prediction
    k_pairs<<<(int)(((size_t)P * 32 + T - 1) / T), T>>>(Wl, bl, out, P);
}

// round 11
// speedup vs baseline: 1.7247x; 1.6039x over previous
#include <cuda_runtime.h>
#include <math.h>

#define NN 50000          // nodes
#define NF 128            // feature width
#define NH 256            // hidden width
#define EMAX 800000
#define PMAX 100000
#define SCAN_B 1024
#define NBLK ((NN + SCAN_B - 1) / SCAN_B)   // 49

// ---- scratch (device globals; no allocation allowed) ----
__device__ int   g_row [EMAX];
__device__ int   g_col [EMAX];
__device__ int   g_eidx[EMAX];              // CSR: src node per (dst-sorted) slot
__device__ int   g_cnt [NN];
__device__ int   g_cur [NN];
__device__ int   g_rowptr[NN + 1];
__device__ int   g_bsum[NBLK];
__device__ int   g_ma  [PMAX];
__device__ int   g_mb  [PMAX];
__device__ float g_dinv[NN];
__device__ float g_Y1  [(size_t)NN * NF];   // S @ X
__device__ float g_ta  [NN];                // H1 @ wa   (atomic accum)
__device__ float g_tb  [NN];                // H1 @ wb
__device__ float g_u   [NN];                // S@ta + ca
__device__ float g_v   [NN];                // S@tb + cb
__device__ float g_wa  [NH];                // W2 @ Wl[0:128]
__device__ float g_wb  [NH];                // W2 @ Wl[128:256]
__device__ float g_ca, g_cb;                // b2 . Wl_a , b2 . Wl_b

// ---------------------------------------------------- helpers
// Per-thread dtype sniff: int64 node ids are all in [0, NN); int32 data
// viewed as int64 fuses random pairs into huge values. 8 samples => certain.
__device__ __forceinline__ int sniff_is64(const void* p_) {
    const long long* p = (const long long*)p_;
    int ok = 1;
#pragma unroll
    for (int i = 0; i < 8; i++) {
        long long v = p[i];
        if (v < 0 || v >= NN) ok = 0;
    }
    return ok;
}

__global__ void k_zero() {
    int i = blockIdx.x * blockDim.x + threadIdx.x;
    if (i < NN) { g_cnt[i] = 0; g_cur[i] = 0; g_ta[i] = 0.f; g_tb[i] = 0.f; }
}

// one kernel: convert edges (+count in-degree) AND convert mask pairs
__global__ void k_convert(const void* __restrict__ ei, int E,
                          const void* __restrict__ mask, int P, int EB) {
    int b = blockIdx.x;
    if (b < EB) {
        int e = b * blockDim.x + threadIdx.x;
        if (e >= E) return;
        int r, c;
        if (sniff_is64(ei)) {
            const long long* p = (const long long*)ei;
            r = (int)p[e];
            c = (int)p[(size_t)E + e];
        } else {
            const int* p = (const int*)ei;
            r = p[e];
            c = p[E + e];
        }
        g_row[e] = r;
        g_col[e] = c;
        atomicAdd(&g_cnt[c], 1);
    } else {
        int i = (b - EB) * blockDim.x + threadIdx.x;
        if (i >= P) return;
        int a, c;
        if (sniff_is64(mask)) {
            const long long* p = (const long long*)mask;
            a = (int)p[(size_t)i * 2 + 0];
            c = (int)p[(size_t)i * 2 + 1];
        } else {
            const int* p = (const int*)mask;
            a = p[i * 2 + 0];
            c = p[i * 2 + 1];
        }
        g_ma[i] = a;
        g_mb[i] = c;
    }
}

// ------------------------------------------------- exclusive scan (3-phase)
__global__ __launch_bounds__(SCAN_B)
void k_scan_block() {
    __shared__ int sh[SCAN_B];
    int t = threadIdx.x;
    int idx = blockIdx.x * SCAN_B + t;
    int v = (idx < NN) ? g_cnt[idx] : 0;
    sh[t] = v;
    __syncthreads();
    for (int off = 1; off < SCAN_B; off <<= 1) {
        int add = (t >= off) ? sh[t - off] : 0;
        __syncthreads();
        sh[t] += add;
        __syncthreads();
    }
    if (idx < NN) g_rowptr[idx] = sh[t] - v;
    if (t == SCAN_B - 1) g_bsum[blockIdx.x] = sh[t];
}

__global__ void k_scan_sums() {
    int t = threadIdx.x;                    // 64 threads, NBLK=49 active
    int v = (t < NBLK) ? g_bsum[t] : 0;
    int lane = t & 31, w = t >> 5;
    int x = v;
#pragma unroll
    for (int off = 1; off < 32; off <<= 1) {
        int y = __shfl_up_sync(0xffffffffu, x, off);
        if (lane >= off) x += y;
    }
    __shared__ int wsum[2];
    if (lane == 31) wsum[w] = x;
    __syncthreads();
    int base = (w == 1) ? wsum[0] : 0;
    if (t < NBLK) g_bsum[t] = base + x - v;  // exclusive
}

__global__ void k_finish(int E) {
    int idx = blockIdx.x * blockDim.x + threadIdx.x;
    if (idx < NN) {
        g_rowptr[idx] += g_bsum[idx >> 10];
        g_dinv[idx] = rsqrtf((float)g_cnt[idx] + 1.0f);   // + self loop
    }
    if (idx == 0) g_rowptr[NN] = E;
}

// ------------------------------------------------------------- CSR fill
__global__ void k_fill(int E) {
    int e = blockIdx.x * blockDim.x + threadIdx.x;
    if (e >= E) return;
    int c = g_col[e];
    int pos = g_rowptr[c] + atomicAdd(&g_cur[c], 1);
    g_eidx[pos] = g_row[e];
}

// ------------------------------------------- collapsed layer-2 weights
// wa = W2 @ Wl[0:128], wb = W2 @ Wl[128:256]; ca = b2.Wl_a, cb = b2.Wl_b
__global__ __launch_bounds__(NH)
void k_wvec(const float* __restrict__ W2, const float* __restrict__ b2,
            const float* __restrict__ Wl) {
    int k = threadIdx.x;                    // 0..255
    float sa = 0.f, sb = 0.f;
#pragma unroll 8
    for (int f = 0; f < NF; f++) {
        float w = W2[k * NF + f];
        sa += w * Wl[f];
        sb += w * Wl[NF + f];
    }
    g_wa[k] = sa;
    g_wb[k] = sb;
    // block-reduce b2 . Wl_a and b2 . Wl_b (first 128 threads contribute)
    __shared__ float ra[NH], rb[NH];
    ra[k] = (k < NF) ? b2[k] * Wl[k] : 0.f;
    rb[k] = (k < NF) ? b2[k] * Wl[NF + k] : 0.f;
    __syncthreads();
    for (int s = NH / 2; s > 0; s >>= 1) {
        if (k < s) { ra[k] += ra[k + s]; rb[k] += rb[k + s]; }
        __syncthreads();
    }
    if (k == 0) { g_ca = ra[0]; g_cb = rb[0]; }
}

// ----------------------------------------------------------------- gather
// warp per node: Y1[n] = dinv[n]^2*X[n] + sum_e dinv[r]*dinv[n]*X[r]
__global__ __launch_bounds__(256)
void k_gather(const float* __restrict__ src, float* __restrict__ dst) {
    int node = (blockIdx.x * blockDim.x + threadIdx.x) >> 5;
    if (node >= NN) return;
    int lane = threadIdx.x & 31;
    float dc = g_dinv[node];

    float4 v = ((const float4*)(src + (size_t)node * NF))[lane];
    float ws = dc * dc;
    float4 acc;
    acc.x = ws * v.x; acc.y = ws * v.y; acc.z = ws * v.z; acc.w = ws * v.w;

    int beg = g_rowptr[node];
    int end = g_rowptr[node + 1];
#pragma unroll 4
    for (int j = beg; j < end; j++) {
        int r = __ldg(&g_eidx[j]);
        float w = __ldg(&g_dinv[r]) * dc;
        float4 u = ((const float4*)(src + (size_t)r * NF))[lane];
        acc.x += w * u.x; acc.y += w * u.y;
        acc.z += w * u.z; acc.w += w * u.w;
    }
    ((float4*)(dst + (size_t)node * NF))[lane] = acc;
}

// --------------------------------------- fused SGEMM + relu + dual dot
// A = Y1 [NN, 128], B = W1 [128, 256]. H1 = relu(A@B + b1) is NOT stored;
// instead accumulate ta[row] += H1[row,:].wa and tb[row] += H1[row,:].wb
// (each 128-col tile contributes its partial; grid.y = 2 tiles cover 256).
__global__ __launch_bounds__(256, 2)
void k_sgemm_fused(const float* __restrict__ A, const float* __restrict__ B,
                   const float* __restrict__ bias, int M, int N, int K) {
    const int BM = 128, BN = 128, BK = 16;
    __shared__ float As[2][BK * BM];   // transposed: As[k][m]
    __shared__ float Bs[2][BK * BN];   // Bs[k][n]

    int tid = threadIdx.x;
    int tx = tid & 15;
    int ty = tid >> 4;
    int rowBlock = blockIdx.x * BM;
    int colBlock = blockIdx.y * BN;

    int fi0 = tid, fi1 = tid + 256;
    int ar0 = fi0 >> 2,  ak0 = (fi0 & 3) << 2;
    int ar1 = fi1 >> 2,  ak1 = (fi1 & 3) << 2;
    int bk0 = fi0 >> 5,  bn0 = (fi0 & 31) << 2;
    int bk1 = fi1 >> 5,  bn1 = (fi1 & 31) << 2;

    float4 ra0, ra1, rb0, rb1;

    auto load_g = [&](int k0) {
        ra0 = make_float4(0.f, 0.f, 0.f, 0.f);
        ra1 = make_float4(0.f, 0.f, 0.f, 0.f);
        int g0 = rowBlock + ar0, g1 = rowBlock + ar1;
        if (g0 < M) ra0 = *(const float4*)(A + (size_t)g0 * K + k0 + ak0);
        if (g1 < M) ra1 = *(const float4*)(A + (size_t)g1 * K + k0 + ak1);
        rb0 = *(const float4*)(B + (size_t)(k0 + bk0) * N + colBlock + bn0);
        rb1 = *(const float4*)(B + (size_t)(k0 + bk1) * N + colBlock + bn1);
    };
    auto store_s = [&](int buf) {
        As[buf][(ak0 + 0) * BM + ar0] = ra0.x;
        As[buf][(ak0 + 1) * BM + ar0] = ra0.y;
        As[buf][(ak0 + 2) * BM + ar0] = ra0.z;
        As[buf][(ak0 + 3) * BM + ar0] = ra0.w;
        As[buf][(ak1 + 0) * BM + ar1] = ra1.x;
        As[buf][(ak1 + 1) * BM + ar1] = ra1.y;
        As[buf][(ak1 + 2) * BM + ar1] = ra1.z;
        As[buf][(ak1 + 3) * BM + ar1] = ra1.w;
        *(float4*)&Bs[buf][bk0 * BN + bn0] = rb0;
        *(float4*)&Bs[buf][bk1 * BN + bn1] = rb1;
    };

    float acc[8][8];
#pragma unroll
    for (int i = 0; i < 8; i++)
#pragma unroll
        for (int j = 0; j < 8; j++) acc[i][j] = 0.0f;

    load_g(0);
    store_s(0);
    __syncthreads();

    int buf = 0;
    for (int k0 = 0; k0 < K; k0 += BK) {
        bool more = (k0 + BK) < K;
        if (more) load_g(k0 + BK);

#pragma unroll
        for (int kk = 0; kk < BK; kk++) {
            float a0[4], a1[4], b0[4], b1[4];
            *(float4*)a0 = *(const float4*)&As[buf][kk * BM + ty * 4];
            *(float4*)a1 = *(const float4*)&As[buf][kk * BM + 64 + ty * 4];
            *(float4*)b0 = *(const float4*)&Bs[buf][kk * BN + tx * 4];
            *(float4*)b1 = *(const float4*)&Bs[buf][kk * BN + 64 + tx * 4];
#pragma unroll
            for (int i = 0; i < 4; i++) {
#pragma unroll
                for (int j = 0; j < 4; j++) {
                    acc[i][j]         += a0[i] * b0[j];
                    acc[i][j + 4]     += a0[i] * b1[j];
                    acc[i + 4][j]     += a1[i] * b0[j];
                    acc[i + 4][j + 4] += a1[i] * b1[j];
                }
            }
        }
        if (more) {
            store_s(buf ^ 1);
            __syncthreads();
            buf ^= 1;
        }
    }

    // epilogue: relu(acc + b1[col]) -> per-row dual dot with wa/wb
    float da[8], db[8];
#pragma unroll
    for (int i = 0; i < 8; i++) { da[i] = 0.f; db[i] = 0.f; }
#pragma unroll
    for (int jh = 0; jh < 2; jh++) {
#pragma unroll
        for (int j = 0; j < 4; j++) {
            int col = colBlock + jh * 64 + tx * 4 + j;
            float bv  = __ldg(&bias[col]);
            float wav = g_wa[col];
            float wbv = g_wb[col];
#pragma unroll
            for (int r8 = 0; r8 < 8; r8++) {
                float h = fmaxf(acc[r8][jh * 4 + j] + bv, 0.f);
                da[r8] += h * wav;
                db[r8] += h * wbv;
            }
        }
    }
    // reduce across the 16 tx lanes (all share the same 8 rows)
#pragma unroll
    for (int r8 = 0; r8 < 8; r8++) {
#pragma unroll
        for (int o = 8; o > 0; o >>= 1) {
            da[r8] += __shfl_xor_sync(0xffffffffu, da[r8], o);
            db[r8] += __shfl_xor_sync(0xffffffffu, db[r8], o);
        }
    }
    if (tx == 0) {
#pragma unroll
        for (int r8 = 0; r8 < 8; r8++) {
            int ih = r8 >> 2, i = r8 & 3;
            int row = rowBlock + ih * 64 + ty * 4 + i;
            if (row < M) {
                atomicAdd(&g_ta[row], da[r8]);
                atomicAdd(&g_tb[row], db[r8]);
            }
        }
    }
}

// ------------------------------------------- scalar propagation (layer 2)
// u[n] = dinv[n]*(dinv[n]*ta[n] + sum_r dinv[r]*ta[r]) + ca   (v likewise)
__global__ void k_gather_scalar() {
    int n = blockIdx.x * blockDim.x + threadIdx.x;
    if (n >= NN) return;
    float dc = g_dinv[n];
    float sa = dc * g_ta[n];
    float sb = dc * g_tb[n];
    int beg = g_rowptr[n], end = g_rowptr[n + 1];
    for (int j = beg; j < end; j++) {
        int r = __ldg(&g_eidx[j]);
        float w = __ldg(&g_dinv[r]);
        sa += w * __ldg(&g_ta[r]);
        sb += w * __ldg(&g_tb[r]);
    }
    g_u[n] = dc * sa + g_ca;
    g_v[n] = dc * sb + g_cb;
}

// --------------------------------------------------------------- pairs
__global__ void k_pairs(const float* __restrict__ bl,
                        float* __restrict__ out, int P) {
    int p = blockIdx.x * blockDim.x + threadIdx.x;
    if (p >= P) return;
    float s = g_u[g_ma[p]] + g_v[g_mb[p]] + bl[0];
    out[p] = 1.0f / (1.0f + expf(-s));
}

// ------------------------------------------------------------------ launch
extern "C" void kernel_launch(void* const* d_in, const int* in_sizes, int n_in,
                              void* d_out, int out_size) {
    const void*  ei   = d_in[0];                 // [2, E] int32 or int64
    const float* X    = (const float*)d_in[1];   // [NN, 128]
    const void*  mask = d_in[2];                 // [P, 2] int32 or int64
    const float* W1   = (const float*)d_in[3];   // [128, 256]
    const float* b1   = (const float*)d_in[4];   // [256]
    const float* W2   = (const float*)d_in[5];   // [256, 128]
    const float* b2   = (const float*)d_in[6];   // [128]
    const float* Wl   = (const float*)d_in[7];   // [256, 1]
    const float* bl   = (const float*)d_in[8];   // [1]
    float* out = (float*)d_out;

    int E = in_sizes[0] / 2;
    int P = out_size;

    float* Y1;
    cudaGetSymbolAddress((void**)&Y1, g_Y1);

    const int T = 256;
    int EB = (E + T - 1) / T;
    int PB = (P + T - 1) / T;

    // prologue: dtype convert + CSR build + collapsed layer-2 weights
    k_zero      <<<(NN + T - 1) / T, T>>>();
    k_convert   <<<EB + PB, T>>>(ei, E, mask, P, EB);
    k_scan_block<<<NBLK, SCAN_B>>>();
    k_scan_sums <<<1, 64>>>();
    k_finish    <<<(NN + T - 1) / T, T>>>(E);
    k_fill      <<<EB, T>>>(E);
    k_wvec      <<<1, NH>>>(W2, b2, Wl);

    // layer 1: Y1 = S @ X ; fused GEMM computes ta = relu(Y1@W1+b1)@wa, tb
    k_gather<<<(NN * 32 + T - 1) / T, T>>>(X, Y1);
    k_sgemm_fused<<<dim3((NN + 127) / 128, NH / 128), 256>>>(Y1, W1, b1,
                                                             NN, NH, NF);

    // collapsed layer 2: scalar CSR propagation, then pair lookups
    k_gather_scalar<<<(NN + T - 1) / T, T>>>();
    k_pairs<<<(P + T - 1) / T, T>>>(bl, out, P);
}

// round 13
// speedup vs baseline: 1.9149x; 1.1102x over previous
#include <cuda_runtime.h>
#include <cuda_bf16.h>
#include <mma.h>
#include <math.h>
#include <stdint.h>

using namespace nvcuda;

#define NN 50000          // nodes
#define NPAD 50048        // padded to 128
#define NF 128            // feature width
#define NH 256            // hidden width
#define EMAX 800000
#define PMAX 100000
#define SCAN_B 1024
#define NBLK ((NN + SCAN_B - 1) / SCAN_B)   // 49

// ---- scratch (device globals; no allocation allowed) ----
__device__ int   g_row [EMAX];
__device__ int   g_col [EMAX];
__device__ int   g_eidx[EMAX];
__device__ int   g_cnt [NN];
__device__ int   g_cur [NN];
__device__ int   g_rowptr[NN + 1];
__device__ int   g_bsum[NBLK];
__device__ int   g_ma  [PMAX];
__device__ int   g_mb  [PMAX];
__device__ float g_dinv[NN];
__device__ __nv_bfloat16 g_Yh[(size_t)NPAD * NF];  // hi(S@X)
__device__ __nv_bfloat16 g_Yl[(size_t)NPAD * NF];  // lo(S@X)
__device__ __nv_bfloat16 g_Wh[(size_t)NF * NH];    // hi(W1)
__device__ __nv_bfloat16 g_Wl[(size_t)NF * NH];    // lo(W1)
__device__ float g_ta  [NN];                // relu(Y1@W1+b1) @ wa  (atomic)
__device__ float g_tb  [NN];
__device__ float g_u   [NN];
__device__ float g_v   [NN];
__device__ float g_wa  [NH];                // W2 @ Wl[0:128]
__device__ float g_wb  [NH];                // W2 @ Wl[128:256]
__device__ float g_ca, g_cb;

// ---------------------------------------------------- prologue kernels
// Per-thread dtype sniff: int64 node ids are all in [0, NN); int32 data
// viewed as int64 fuses random pairs into huge values. 8 samples => certain.
__device__ __forceinline__ int sniff_is64(const void* p_) {
    const long long* p = (const long long*)p_;
    int ok = 1;
#pragma unroll
    for (int i = 0; i < 8; i++) {
        long long v = p[i];
        if (v < 0 || v >= NN) ok = 0;
    }
    return ok;
}

__global__ void k_zero() {
    int i = blockIdx.x * blockDim.x + threadIdx.x;
    if (i < NN) { g_cnt[i] = 0; g_cur[i] = 0; g_ta[i] = 0.f; g_tb[i] = 0.f; }
}

// blocks [0,EB): edges; [EB,EB+PB): mask; EB+PB: collapsed weights; +1: W1 split
__global__ void k_convert(const void* __restrict__ ei, int E,
                          const void* __restrict__ mask, int P, int EB, int PB,
                          const float* __restrict__ W1,
                          const float* __restrict__ W2,
                          const float* __restrict__ b2,
                          const float* __restrict__ Wl) {
    int b = blockIdx.x;
    if (b < EB) {
        int e = b * blockDim.x + threadIdx.x;
        if (e >= E) return;
        int r, c;
        if (sniff_is64(ei)) {
            const long long* p = (const long long*)ei;
            r = (int)p[e];
            c = (int)p[(size_t)E + e];
        } else {
            const int* p = (const int*)ei;
            r = p[e];
            c = p[E + e];
        }
        g_row[e] = r;
        g_col[e] = c;
        atomicAdd(&g_cnt[c], 1);
    } else if (b < EB + PB) {
        int i = (b - EB) * blockDim.x + threadIdx.x;
        if (i >= P) return;
        int a, c;
        if (sniff_is64(mask)) {
            const long long* p = (const long long*)mask;
            a = (int)p[(size_t)i * 2 + 0];
            c = (int)p[(size_t)i * 2 + 1];
        } else {
            const int* p = (const int*)mask;
            a = p[i * 2 + 0];
            c = p[i * 2 + 1];
        }
        g_ma[i] = a;
        g_mb[i] = c;
    } else if (b == EB + PB) {
        // collapsed layer-2 weights: wa = W2@Wl_a, wb = W2@Wl_b, ca/cb
        int k = threadIdx.x;                // 0..255
        float sa = 0.f, sb = 0.f;
#pragma unroll 8
        for (int f = 0; f < NF; f++) {
            float w = W2[k * NF + f];
            sa += w * Wl[f];
            sb += w * Wl[NF + f];
        }
        g_wa[k] = sa;
        g_wb[k] = sb;
        __shared__ float ra[NH], rb[NH];
        ra[k] = (k < NF) ? b2[k] * Wl[k] : 0.f;
        rb[k] = (k < NF) ? b2[k] * Wl[NF + k] : 0.f;
        __syncthreads();
        for (int s = NH / 2; s > 0; s >>= 1) {
            if (k < s) { ra[k] += ra[k + s]; rb[k] += rb[k + s]; }
            __syncthreads();
        }
        if (k == 0) { g_ca = ra[0]; g_cb = rb[0]; }
    } else {
        // split W1 into bf16 hi/lo
        for (int idx = threadIdx.x; idx < NF * NH; idx += blockDim.x) {
            float v = W1[idx];
            __nv_bfloat16 h = __float2bfloat16(v);
            g_Wh[idx] = h;
            g_Wl[idx] = __float2bfloat16(v - __bfloat162float(h));
        }
    }
}

__global__ __launch_bounds__(SCAN_B)
void k_scan_block() {
    __shared__ int sh[SCAN_B];
    int t = threadIdx.x;
    int idx = blockIdx.x * SCAN_B + t;
    int v = (idx < NN) ? g_cnt[idx] : 0;
    sh[t] = v;
    __syncthreads();
    for (int off = 1; off < SCAN_B; off <<= 1) {
        int add = (t >= off) ? sh[t - off] : 0;
        __syncthreads();
        sh[t] += add;
        __syncthreads();
    }
    if (idx < NN) g_rowptr[idx] = sh[t] - v;
    if (t == SCAN_B - 1) g_bsum[blockIdx.x] = sh[t];
}

// grid-wide: each block redundantly prefixes the 49 block sums, then fixup+dinv
__global__ void k_finish(int E) {
    __shared__ int pre[64];
    int t = threadIdx.x;
    if (t < 64) {
        int acc = 0;
        for (int b = 0; b < t && b < NBLK; b++) acc += g_bsum[b];
        pre[t] = acc;
    }
    __syncthreads();
    int idx = blockIdx.x * blockDim.x + t;
    if (idx < NN) {
        g_rowptr[idx] += pre[idx >> 10];
        g_dinv[idx] = rsqrtf((float)g_cnt[idx] + 1.0f);
    }
    if (idx == 0) g_rowptr[NN] = E;
}

__global__ void k_fill(int E) {
    int e = blockIdx.x * blockDim.x + threadIdx.x;
    if (e >= E) return;
    int c = g_col[e];
    int pos = g_rowptr[c] + atomicAdd(&g_cur[c], 1);
    g_eidx[pos] = g_row[e];
}

// --------------------------------------------- gather (emits bf16 hi/lo)
__global__ __launch_bounds__(256)
void k_gather(const float* __restrict__ src) {
    int node = (blockIdx.x * blockDim.x + threadIdx.x) >> 5;
    if (node >= NN) return;
    int lane = threadIdx.x & 31;
    float dc = g_dinv[node];

    float4 v = ((const float4*)(src + (size_t)node * NF))[lane];
    float ws = dc * dc;
    float4 acc;
    acc.x = ws * v.x; acc.y = ws * v.y; acc.z = ws * v.z; acc.w = ws * v.w;

    int beg = g_rowptr[node];
    int end = g_rowptr[node + 1];
#pragma unroll 4
    for (int j = beg; j < end; j++) {
        int r = __ldg(&g_eidx[j]);
        float w = __ldg(&g_dinv[r]) * dc;
        float4 u = ((const float4*)(src + (size_t)r * NF))[lane];
        acc.x += w * u.x; acc.y += w * u.y;
        acc.z += w * u.z; acc.w += w * u.w;
    }
    // split to bf16 hi/lo and store (4 cols per lane)
    __nv_bfloat16 h0 = __float2bfloat16(acc.x);
    __nv_bfloat16 h1 = __float2bfloat16(acc.y);
    __nv_bfloat16 h2 = __float2bfloat16(acc.z);
    __nv_bfloat16 h3 = __float2bfloat16(acc.w);
    __nv_bfloat16 l0 = __float2bfloat16(acc.x - __bfloat162float(h0));
    __nv_bfloat16 l1 = __float2bfloat16(acc.y - __bfloat162float(h1));
    __nv_bfloat16 l2 = __float2bfloat16(acc.z - __bfloat162float(h2));
    __nv_bfloat16 l3 = __float2bfloat16(acc.w - __bfloat162float(h3));
    __nv_bfloat162 hp0 = __halves2bfloat162(h0, h1);
    __nv_bfloat162 hp1 = __halves2bfloat162(h2, h3);
    __nv_bfloat162 lp0 = __halves2bfloat162(l0, l1);
    __nv_bfloat162 lp1 = __halves2bfloat162(l2, l3);
    uint2 hv = make_uint2(*(uint32_t*)&hp0, *(uint32_t*)&hp1);
    uint2 lv = make_uint2(*(uint32_t*)&lp0, *(uint32_t*)&lp1);
    *(uint2*)(g_Yh + (size_t)node * NF + lane * 4) = hv;
    *(uint2*)(g_Yl + (size_t)node * NF + lane * 4) = lv;
}

// ==================== split-bf16 wmma GEMM + relu + dual dot
// CTA tile 128 rows x 128 cols (grid 391 x 2); 8 warps as 2x4 -> 64x32 each.
// D = Ah*Bh + Ah*Bl + Al*Bh, fp32 accum.
#define LDA 136                              // bf16 elems per smem row (pad)
#define SM_WMMA (4 * 128 * LDA * 2)          // Ah, Al, Bh, Bl = 139264 B

__global__ __launch_bounds__(256, 1)
void k_gemm_wmma(const float* __restrict__ b1, int M) {
    extern __shared__ char smc[];
    __nv_bfloat16* Ah = (__nv_bfloat16*)smc;
    __nv_bfloat16* Al = Ah + 128 * LDA;
    __nv_bfloat16* Bh = Al + 128 * LDA;
    __nv_bfloat16* Bl = Bh + 128 * LDA;
    float* Csm = (float*)smc;                // reuse for epilogue (69 KB)

    int tid = threadIdx.x;
    int rowBlock = blockIdx.x * 128;
    int colBlock = blockIdx.y * 128;

    // stage A tile (rows rowBlock..+127, k 0..127), 8 bf16 per uint4
    for (int idx = tid; idx < 128 * 16; idx += 256) {
        int r = idx >> 4, c8 = (idx & 15) << 3;
        size_t g = (size_t)(rowBlock + r) * NF + c8;
        *(uint4*)(Ah + r * LDA + c8) = *(const uint4*)(g_Yh + g);
        *(uint4*)(Al + r * LDA + c8) = *(const uint4*)(g_Yl + g);
    }
    // stage B tile (k 0..127, cols colBlock..+127)
    for (int idx = tid; idx < 128 * 16; idx += 256) {
        int k = idx >> 4, c8 = (idx & 15) << 3;
        size_t g = (size_t)k * NH + colBlock + c8;
        *(uint4*)(Bh + k * LDA + c8) = *(const uint4*)(g_Wh + g);
        *(uint4*)(Bl + k * LDA + c8) = *(const uint4*)(g_Wl + g);
    }
    __syncthreads();

    int w = tid >> 5;
    int wr = w >> 2, wc = w & 3;             // 2 row-groups x 4 col-groups

    wmma::fragment<wmma::accumulator, 16, 16, 16, float> C[4][2];
#pragma unroll
    for (int i = 0; i < 4; i++)
#pragma unroll
        for (int j = 0; j < 2; j++) wmma::fill_fragment(C[i][j], 0.0f);

    for (int ks = 0; ks < 128; ks += 16) {
        wmma::fragment<wmma::matrix_a, 16, 16, 16, __nv_bfloat16, wmma::row_major> ah[4], al[4];
        wmma::fragment<wmma::matrix_b, 16, 16, 16, __nv_bfloat16, wmma::row_major> bh[2], bl[2];
#pragma unroll
        for (int i = 0; i < 4; i++) {
            wmma::load_matrix_sync(ah[i], Ah + (wr * 64 + i * 16) * LDA + ks, LDA);
            wmma::load_matrix_sync(al[i], Al + (wr * 64 + i * 16) * LDA + ks, LDA);
        }
#pragma unroll
        for (int j = 0; j < 2; j++) {
            wmma::load_matrix_sync(bh[j], Bh + ks * LDA + wc * 32 + j * 16, LDA);
            wmma::load_matrix_sync(bl[j], Bl + ks * LDA + wc * 32 + j * 16, LDA);
        }
#pragma unroll
        for (int i = 0; i < 4; i++)
#pragma unroll
            for (int j = 0; j < 2; j++) {
                wmma::mma_sync(C[i][j], ah[i], bh[j], C[i][j]);
                wmma::mma_sync(C[i][j], ah[i], bl[j], C[i][j]);
                wmma::mma_sync(C[i][j], al[i], bh[j], C[i][j]);
            }
    }
    __syncthreads();                          // done reading A/B smem

#pragma unroll
    for (int i = 0; i < 4; i++)
#pragma unroll
        for (int j = 0; j < 2; j++)
            wmma::store_matrix_sync(Csm + (wr * 64 + i * 16) * LDA + wc * 32 + j * 16,
                                    C[i][j], LDA, wmma::mem_row_major);
    __syncthreads();

    // epilogue: relu(C + b1) dot wa/wb; 2 threads per row (64 cols each)
    int r = tid >> 1, h = tid & 1;
    float da = 0.f, db = 0.f;
    int cbase = h * 64;
#pragma unroll 8
    for (int c = 0; c < 64; c++) {
        int col = colBlock + cbase + c;
        float v = fmaxf(Csm[r * LDA + cbase + c] + __ldg(&b1[col]), 0.f);
        da += v * g_wa[col];
        db += v * g_wb[col];
    }
    da += __shfl_xor_sync(0xffffffffu, da, 1);
    db += __shfl_xor_sync(0xffffffffu, db, 1);
    if (h == 0) {
        int row = rowBlock + r;
        if (row < M) {
            atomicAdd(&g_ta[row], da);
            atomicAdd(&g_tb[row], db);
        }
    }
}

// ------------------------------------------- scalar propagation (layer 2)
__global__ void k_gather_scalar() {
    int n = blockIdx.x * blockDim.x + threadIdx.x;
    if (n >= NN) return;
    float dc = g_dinv[n];
    float sa = dc * g_ta[n];
    float sb = dc * g_tb[n];
    int beg = g_rowptr[n], end = g_rowptr[n + 1];
    for (int j = beg; j < end; j++) {
        int r = __ldg(&g_eidx[j]);
        float w = __ldg(&g_dinv[r]);
        sa += w * __ldg(&g_ta[r]);
        sb += w * __ldg(&g_tb[r]);
    }
    g_u[n] = dc * sa + g_ca;
    g_v[n] = dc * sb + g_cb;
}

__global__ void k_pairs(const float* __restrict__ bl,
                        float* __restrict__ out, int P) {
    int p = blockIdx.x * blockDim.x + threadIdx.x;
    if (p >= P) return;
    float s = g_u[g_ma[p]] + g_v[g_mb[p]] + bl[0];
    out[p] = 1.0f / (1.0f + expf(-s));
}

// ------------------------------------------------------------------ launch
extern "C" void kernel_launch(void* const* d_in, const int* in_sizes, int n_in,
                              void* d_out, int out_size) {
    const void*  ei   = d_in[0];
    const float* X    = (const float*)d_in[1];
    const void*  mask = d_in[2];
    const float* W1   = (const float*)d_in[3];
    const float* b1   = (const float*)d_in[4];
    const float* W2   = (const float*)d_in[5];
    const float* b2   = (const float*)d_in[6];
    const float* Wl   = (const float*)d_in[7];
    const float* bl   = (const float*)d_in[8];
    float* out = (float*)d_out;

    int E = in_sizes[0] / 2;
    int P = out_size;

    cudaFuncSetAttribute(k_gemm_wmma,
                         cudaFuncAttributeMaxDynamicSharedMemorySize, SM_WMMA);

    const int T = 256;
    int EB = (E + T - 1) / T;
    int PB = (P + T - 1) / T;

    k_zero      <<<(NN + T - 1) / T, T>>>();
    k_convert   <<<EB + PB + 2, T>>>(ei, E, mask, P, EB, PB, W1, W2, b2, Wl);
    k_scan_block<<<NBLK, SCAN_B>>>();
    k_finish    <<<(NN + T - 1) / T, T>>>(E);
    k_fill      <<<EB, T>>>(E);

    k_gather<<<(NN * 32 + T - 1) / T, T>>>(X);
    k_gemm_wmma<<<dim3(NPAD / 128, 2), 256, SM_WMMA>>>(b1, NN);

    k_gather_scalar<<<(NN + T - 1) / T, T>>>();
    k_pairs<<<(P + T - 1) / T, T>>>(bl, out, P);
}

// round 15
// speedup vs baseline: 1.9812x; 1.0347x over previous
#include <cuda_runtime.h>
#include <cuda_bf16.h>
#include <mma.h>
#include <math.h>
#include <stdint.h>

using namespace nvcuda;

#define NN 50000          // nodes
#define NPAD 50048        // padded to 128
#define NF 128            // feature width
#define NH 256            // hidden width
#define EMAX 800000
#define PMAX 100000
#define SCAN_B 1024
#define NBLK ((NN + SCAN_B - 1) / SCAN_B)   // 49

// ---- scratch (device globals; no allocation allowed) ----
__device__ int   g_row [EMAX];
__device__ int   g_col [EMAX];
__device__ int   g_eidx[EMAX];
__device__ int   g_cnt [NN + 64];           // tail [NN..NN+63] = scan flags
__device__ int   g_cur [NN];                // fill cursors (init = rowptr)
__device__ int   g_rowptr[NN + 1];
__device__ int   g_ma  [PMAX];
__device__ int   g_mb  [PMAX];
__device__ float g_dinv[NN];
__device__ __nv_bfloat16 g_Yh[(size_t)NPAD * NF];  // hi(S@X)
__device__ __nv_bfloat16 g_Yl[(size_t)NPAD * NF];  // lo(S@X)
__device__ __nv_bfloat16 g_Wh[(size_t)NF * NH];    // hi(W1)
__device__ __nv_bfloat16 g_Wl[(size_t)NF * NH];    // lo(W1)
__device__ float g_ta  [NN];                // relu(Y1@W1+b1) @ wa
__device__ float g_tb  [NN];
__device__ float g_u   [NN];
__device__ float g_v   [NN];
__device__ float g_wa  [NH];                // W2 @ Wl[0:128]
__device__ float g_wb  [NH];                // W2 @ Wl[128:256]
__device__ float g_ca, g_cb;

// ---------------------------------------------------- prologue kernels
// Per-thread dtype sniff: int64 node ids are all in [0, NN); int32 data
// viewed as int64 fuses random pairs into huge values. 8 samples => certain.
__device__ __forceinline__ int sniff_is64(const void* p_) {
    const long long* p = (const long long*)p_;
    int ok = 1;
#pragma unroll
    for (int i = 0; i < 8; i++) {
        long long v = p[i];
        if (v < 0 || v >= NN) ok = 0;
    }
    return ok;
}

// blocks [0,EB): edges; [EB,EB+PB): mask; EB+PB: collapsed weights; +1: W1 split
__global__ void k_convert(const void* __restrict__ ei, int E,
                          const void* __restrict__ mask, int P, int EB, int PB,
                          const float* __restrict__ W1,
                          const float* __restrict__ W2,
                          const float* __restrict__ b2,
                          const float* __restrict__ Wl) {
    int b = blockIdx.x;
    if (b < EB) {
        int e = b * blockDim.x + threadIdx.x;
        if (e >= E) return;
        int r, c;
        if (sniff_is64(ei)) {
            const long long* p = (const long long*)ei;
            r = (int)p[e];
            c = (int)p[(size_t)E + e];
        } else {
            const int* p = (const int*)ei;
            r = p[e];
            c = p[E + e];
        }
        g_row[e] = r;
        g_col[e] = c;
        atomicAdd(&g_cnt[c], 1);
    } else if (b < EB + PB) {
        int i = (b - EB) * blockDim.x + threadIdx.x;
        if (i >= P) return;
        int a, c;
        if (sniff_is64(mask)) {
            const long long* p = (const long long*)mask;
            a = (int)p[(size_t)i * 2 + 0];
            c = (int)p[(size_t)i * 2 + 1];
        } else {
            const int* p = (const int*)mask;
            a = p[i * 2 + 0];
            c = p[i * 2 + 1];
        }
        g_ma[i] = a;
        g_mb[i] = c;
    } else if (b == EB + PB) {
        // collapsed layer-2 weights: wa = W2@Wl_a, wb = W2@Wl_b, ca/cb
        int k = threadIdx.x;                // 0..255
        float sa = 0.f, sb = 0.f;
#pragma unroll 8
        for (int f = 0; f < NF; f++) {
            float w = W2[k * NF + f];
            sa += w * Wl[f];
            sb += w * Wl[NF + f];
        }
        g_wa[k] = sa;
        g_wb[k] = sb;
        __shared__ float ra[NH], rb[NH];
        ra[k] = (k < NF) ? b2[k] * Wl[k] : 0.f;
        rb[k] = (k < NF) ? b2[k] * Wl[NF + k] : 0.f;
        __syncthreads();
        for (int s = NH / 2; s > 0; s >>= 1) {
            if (k < s) { ra[k] += ra[k + s]; rb[k] += rb[k + s]; }
            __syncthreads();
        }
        if (k == 0) { g_ca = ra[0]; g_cb = rb[0]; }
    } else {
        // split W1 into bf16 hi/lo
        for (int idx = threadIdx.x; idx < NF * NH; idx += blockDim.x) {
            float v = W1[idx];
            __nv_bfloat16 h = __float2bfloat16(v);
            g_Wh[idx] = h;
            g_Wl[idx] = __float2bfloat16(v - __bfloat162float(h));
        }
    }
}

// --------------- fused scan: local scan + decoupled lookback + outputs
// 49 blocks (all co-resident). Publishes agg+1 into g_cnt[NN+b]; each block
// spin-reads all predecessors. Writes rowptr, cur (=rowptr), dinv.
__global__ __launch_bounds__(SCAN_B)
void k_scan(int E) {
    __shared__ int sh[SCAN_B];
    __shared__ int sbase[32];
    int t = threadIdx.x;
    int b = blockIdx.x;
    int idx = b * SCAN_B + t;
    int v = (idx < NN) ? g_cnt[idx] : 0;
    sh[t] = v;
    __syncthreads();
    for (int off = 1; off < SCAN_B; off <<= 1) {
        int add = (t >= off) ? sh[t - off] : 0;
        __syncthreads();
        sh[t] += add;
        __syncthreads();
    }
    int excl = sh[t] - v;
    // publish aggregate (value+1 so 0 == not-ready; flags zeroed by memset)
    if (t == SCAN_B - 1)
        atomicExch(&g_cnt[NN + b], sh[t] + 1);
    // lookback: thread t (< b) spins on predecessor t's aggregate
    int part = 0;
    if (t < b) {
        volatile int* f = &g_cnt[NN + t];
        int x;
        while ((x = *f) == 0) { }
        part = x - 1;
    }
    // warp-reduce partials then combine across warps (t < 49 contribute)
    if (t < 64) {
#pragma unroll
        for (int o = 16; o > 0; o >>= 1)
            part += __shfl_xor_sync(0xffffffffu, part, o);
        if ((t & 31) == 0) sbase[t >> 5] = part;
    }
    __syncthreads();
    int base = sbase[0] + sbase[1];
    if (idx < NN) {
        int rp = excl + base;
        g_rowptr[idx] = rp;
        g_cur[idx]    = rp;
        g_dinv[idx]   = rsqrtf((float)g_cnt[idx] + 1.0f);
    }
    if (b == 0 && t == 0) g_rowptr[NN] = E;
}

__global__ void k_fill(int E) {
    int e = blockIdx.x * blockDim.x + threadIdx.x;
    if (e >= E) return;
    int pos = atomicAdd(&g_cur[g_col[e]], 1);
    g_eidx[pos] = g_row[e];
}

// --------------------------------------------- gather (emits bf16 hi/lo)
__global__ __launch_bounds__(256)
void k_gather(const float* __restrict__ src) {
    int node = (blockIdx.x * blockDim.x + threadIdx.x) >> 5;
    if (node >= NN) return;
    int lane = threadIdx.x & 31;
    float dc = g_dinv[node];

    float4 v = ((const float4*)(src + (size_t)node * NF))[lane];
    float ws = dc * dc;
    float4 acc;
    acc.x = ws * v.x; acc.y = ws * v.y; acc.z = ws * v.z; acc.w = ws * v.w;

    int beg = g_rowptr[node];
    int end = g_rowptr[node + 1];
#pragma unroll 4
    for (int j = beg; j < end; j++) {
        int r = __ldg(&g_eidx[j]);
        float w = __ldg(&g_dinv[r]) * dc;
        float4 u = ((const float4*)(src + (size_t)r * NF))[lane];
        acc.x += w * u.x; acc.y += w * u.y;
        acc.z += w * u.z; acc.w += w * u.w;
    }
    __nv_bfloat16 h0 = __float2bfloat16(acc.x);
    __nv_bfloat16 h1 = __float2bfloat16(acc.y);
    __nv_bfloat16 h2 = __float2bfloat16(acc.z);
    __nv_bfloat16 h3 = __float2bfloat16(acc.w);
    __nv_bfloat16 l0 = __float2bfloat16(acc.x - __bfloat162float(h0));
    __nv_bfloat16 l1 = __float2bfloat16(acc.y - __bfloat162float(h1));
    __nv_bfloat16 l2 = __float2bfloat16(acc.z - __bfloat162float(h2));
    __nv_bfloat16 l3 = __float2bfloat16(acc.w - __bfloat162float(h3));
    __nv_bfloat162 hp0 = __halves2bfloat162(h0, h1);
    __nv_bfloat162 hp1 = __halves2bfloat162(h2, h3);
    __nv_bfloat162 lp0 = __halves2bfloat162(l0, l1);
    __nv_bfloat162 lp1 = __halves2bfloat162(l2, l3);
    uint2 hv = make_uint2(*(uint32_t*)&hp0, *(uint32_t*)&hp1);
    uint2 lv = make_uint2(*(uint32_t*)&lp0, *(uint32_t*)&lp1);
    *(uint2*)(g_Yh + (size_t)node * NF + lane * 4) = hv;
    *(uint2*)(g_Yl + (size_t)node * NF + lane * 4) = lv;
}

// ==================== split-bf16 wmma GEMM + relu + dual dot (single pass)
// CTA: 128 rows x all 256 cols (two 128-col halves staged in turn).
// D = Ah*Bh + Ah*Bl + Al*Bh, fp32 accum. Plain stores to ta/tb (no atomics).
#define LDA 136                              // bf16 elems per smem row (pad)
#define SM_A    (2 * 128 * LDA * 2)          // Ah + Al = 69632 B
#define SM_B    (2 * 128 * LDA * 2)          // Bh + Bl = 69632 B (also Csm)
#define SM_WMMA (SM_A + SM_B)                // 139264 B

__global__ __launch_bounds__(256, 1)
void k_gemm_wmma(const float* __restrict__ b1, int M) {
    extern __shared__ char smc[];
    __nv_bfloat16* Ah = (__nv_bfloat16*)smc;
    __nv_bfloat16* Al = Ah + 128 * LDA;
    __nv_bfloat16* Bh = (__nv_bfloat16*)(smc + SM_A);
    __nv_bfloat16* Bl = Bh + 128 * LDA;
    float* Csm = (float*)(smc + SM_A);       // overlays B after compute

    int tid = threadIdx.x;
    int rowBlock = blockIdx.x * 128;
    int w = tid >> 5;
    int wr = w >> 2, wc = w & 3;             // 2 row-groups x 4 col-groups
    int er = tid >> 1, eh = tid & 1;         // epilogue: 2 threads / row

    // stage A tile once
    for (int idx = tid; idx < 128 * 16; idx += 256) {
        int r = idx >> 4, c8 = (idx & 15) << 3;
        size_t g = (size_t)(rowBlock + r) * NF + c8;
        *(uint4*)(Ah + r * LDA + c8) = *(const uint4*)(g_Yh + g);
        *(uint4*)(Al + r * LDA + c8) = *(const uint4*)(g_Yl + g);
    }

    float da = 0.f, db = 0.f;

#pragma unroll
    for (int half = 0; half < 2; half++) {
        int colBlock = half * 128;
        // stage B for this half
        for (int idx = tid; idx < 128 * 16; idx += 256) {
            int k = idx >> 4, c8 = (idx & 15) << 3;
            size_t g = (size_t)k * NH + colBlock + c8;
            *(uint4*)(Bh + k * LDA + c8) = *(const uint4*)(g_Wh + g);
            *(uint4*)(Bl + k * LDA + c8) = *(const uint4*)(g_Wl + g);
        }
        __syncthreads();

        wmma::fragment<wmma::accumulator, 16, 16, 16, float> C[4][2];
#pragma unroll
        for (int i = 0; i < 4; i++)
#pragma unroll
            for (int j = 0; j < 2; j++) wmma::fill_fragment(C[i][j], 0.0f);

        for (int ks = 0; ks < 128; ks += 16) {
            wmma::fragment<wmma::matrix_a, 16, 16, 16, __nv_bfloat16, wmma::row_major> ah[4], al[4];
            wmma::fragment<wmma::matrix_b, 16, 16, 16, __nv_bfloat16, wmma::row_major> bh[2], bl[2];
#pragma unroll
            for (int i = 0; i < 4; i++) {
                wmma::load_matrix_sync(ah[i], Ah + (wr * 64 + i * 16) * LDA + ks, LDA);
                wmma::load_matrix_sync(al[i], Al + (wr * 64 + i * 16) * LDA + ks, LDA);
            }
#pragma unroll
            for (int j = 0; j < 2; j++) {
                wmma::load_matrix_sync(bh[j], Bh + ks * LDA + wc * 32 + j * 16, LDA);
                wmma::load_matrix_sync(bl[j], Bl + ks * LDA + wc * 32 + j * 16, LDA);
            }
#pragma unroll
            for (int i = 0; i < 4; i++)
#pragma unroll
                for (int j = 0; j < 2; j++) {
                    wmma::mma_sync(C[i][j], ah[i], bh[j], C[i][j]);
                    wmma::mma_sync(C[i][j], ah[i], bl[j], C[i][j]);
                    wmma::mma_sync(C[i][j], al[i], bh[j], C[i][j]);
                }
        }
        __syncthreads();                      // B reads done

#pragma unroll
        for (int i = 0; i < 4; i++)
#pragma unroll
            for (int j = 0; j < 2; j++)
                wmma::store_matrix_sync(Csm + (wr * 64 + i * 16) * LDA + wc * 32 + j * 16,
                                        C[i][j], LDA, wmma::mem_row_major);
        __syncthreads();

        // epilogue: relu(C + b1) dot wa/wb
        int cbase = eh * 64;
#pragma unroll 8
        for (int c = 0; c < 64; c++) {
            int col = colBlock + cbase + c;
            float vv = fmaxf(Csm[er * LDA + cbase + c] + __ldg(&b1[col]), 0.f);
            da += vv * g_wa[col];
            db += vv * g_wb[col];
        }
        __syncthreads();                      // Csm reads done (before restage)
    }

    da += __shfl_xor_sync(0xffffffffu, da, 1);
    db += __shfl_xor_sync(0xffffffffu, db, 1);
    if (eh == 0) {
        int row = rowBlock + er;
        if (row < M) { g_ta[row] = da; g_tb[row] = db; }
    }
}

// ------------------------------------------- scalar propagation (layer 2)
__global__ void k_gather_scalar() {
    int n = blockIdx.x * blockDim.x + threadIdx.x;
    if (n >= NN) return;
    float dc = g_dinv[n];
    float sa = dc * g_ta[n];
    float sb = dc * g_tb[n];
    int beg = g_rowptr[n], end = g_rowptr[n + 1];
    for (int j = beg; j < end; j++) {
        int r = __ldg(&g_eidx[j]);
        float w = __ldg(&g_dinv[r]);
        sa += w * __ldg(&g_ta[r]);
        sb += w * __ldg(&g_tb[r]);
    }
    g_u[n] = dc * sa + g_ca;
    g_v[n] = dc * sb + g_cb;
}

__global__ void k_pairs(const float* __restrict__ bl,
                        float* __restrict__ out, int P) {
    int p = blockIdx.x * blockDim.x + threadIdx.x;
    if (p >= P) return;
    float s = g_u[g_ma[p]] + g_v[g_mb[p]] + bl[0];
    out[p] = 1.0f / (1.0f + expf(-s));
}

// ------------------------------------------------------------------ launch
extern "C" void kernel_launch(void* const* d_in, const int* in_sizes, int n_in,
                              void* d_out, int out_size) {
    const void*  ei   = d_in[0];
    const float* X    = (const float*)d_in[1];
    const void*  mask = d_in[2];
    const float* W1   = (const float*)d_in[3];
    const float* b1   = (const float*)d_in[4];
    const float* W2   = (const float*)d_in[5];
    const float* b2   = (const float*)d_in[6];
    const float* Wl   = (const float*)d_in[7];
    const float* bl   = (const float*)d_in[8];
    float* out = (float*)d_out;

    int E = in_sizes[0] / 2;
    int P = out_size;

    cudaFuncSetAttribute(k_gemm_wmma,
                         cudaFuncAttributeMaxDynamicSharedMemorySize, SM_WMMA);

    void* cnt_addr = nullptr;
    cudaGetSymbolAddress(&cnt_addr, g_cnt);

    const int T = 256;
    int EB = (E + T - 1) / T;
    int PB = (P + T - 1) / T;

    // zero degree counts + scan flags in one async memset (graph-capturable)
    cudaMemsetAsync(cnt_addr, 0, sizeof(int) * (NN + 64), 0);

    k_convert<<<EB + PB + 2, T>>>(ei, E, mask, P, EB, PB, W1, W2, b2, Wl);
    k_scan   <<<NBLK, SCAN_B>>>(E);
    k_fill   <<<EB, T>>>(E);

    k_gather<<<(NN * 32 + T - 1) / T, T>>>(X);
    k_gemm_wmma<<<NPAD / 128, 256, SM_WMMA>>>(b1, NN);

    k_gather_scalar<<<(NN + T - 1) / T, T>>>();
    k_pairs<<<(P + T - 1) / T, T>>>(bl, out, P);
}